// round 3
// baseline (speedup 1.0000x reference)
#include <cuda_runtime.h>

#define STATE_DIM 16

// Fused masked copy: per-warp flag (shuffle reduction, no __syncthreads),
// data loads issued first so flag latency fully overlaps load latency.
__global__ void __launch_bounds__(256, 8)
fused_masked_copy_kernel(const float4* __restrict__ x,
                         float4* __restrict__ out,
                         const float* __restrict__ Bs, const float* __restrict__ Cs,
                         const float* __restrict__ Ba, const float* __restrict__ Ca,
                         const float* __restrict__ Be, const float* __restrict__ Ce,
                         int n_vec) {
    const int stride = blockDim.x;
    const int base = blockIdx.x * (stride * 4) + threadIdx.x;
    const int lane = threadIdx.x & 31;

    // ---- flag operand loads (independent of data loads; overlap) ----
    float p1 = 0.f, p2 = 0.f, p3 = 0.f;
    if (lane < STATE_DIM) {
        p1 = Bs[lane] * Cs[lane];
        p2 = Ba[lane] * Ca[lane];
        p3 = Be[lane] * Ce[lane];
    }

    // Uniform per-grid branch (all blocks except possibly last take fast path).
    if (base + 3 * stride < n_vec) {
        // ---- data loads: 4 independent LDG.128 front-batched ----
        float4 v0 = x[base];
        float4 v1 = x[base + stride];
        float4 v2 = x[base + 2 * stride];
        float4 v3 = x[base + 3 * stride];

        // ---- warp reduction of the three 16-element dots (lanes 0..15) ----
#pragma unroll
        for (int o = 8; o > 0; o >>= 1) {
            p1 += __shfl_down_sync(0xffffffffu, p1, o);
            p2 += __shfl_down_sync(0xffffffffu, p2, o);
            p3 += __shfl_down_sync(0xffffffffu, p3, o);
        }
        float k1 = __shfl_sync(0xffffffffu, p1, 0);
        float k2 = __shfl_sync(0xffffffffu, p2, 0);
        float k3 = __shfl_sync(0xffffffffu, p3, 0);
        const float f = (k1 > 0.f && k2 > 0.f && k3 > 0.f) ? 1.0f : 0.0f;

        v0.x *= f; v0.y *= f; v0.z *= f; v0.w *= f;
        v1.x *= f; v1.y *= f; v1.z *= f; v1.w *= f;
        v2.x *= f; v2.y *= f; v2.z *= f; v2.w *= f;
        v3.x *= f; v3.y *= f; v3.z *= f; v3.w *= f;

        out[base]              = v0;
        out[base + stride]     = v1;
        out[base + 2 * stride] = v2;
        out[base + 3 * stride] = v3;
    } else {
        // Tail path (not taken for the benchmarked shape: exact fit).
#pragma unroll
        for (int o = 8; o > 0; o >>= 1) {
            p1 += __shfl_down_sync(0xffffffffu, p1, o);
            p2 += __shfl_down_sync(0xffffffffu, p2, o);
            p3 += __shfl_down_sync(0xffffffffu, p3, o);
        }
        float k1 = __shfl_sync(0xffffffffu, p1, 0);
        float k2 = __shfl_sync(0xffffffffu, p2, 0);
        float k3 = __shfl_sync(0xffffffffu, p3, 0);
        const float f = (k1 > 0.f && k2 > 0.f && k3 > 0.f) ? 1.0f : 0.0f;
#pragma unroll
        for (int k = 0; k < 4; ++k) {
            int i = base + k * stride;
            if (i < n_vec) {
                float4 v = x[i];
                v.x *= f; v.y *= f; v.z *= f; v.w *= f;
                out[i] = v;
            }
        }
    }
}

extern "C" void kernel_launch(void* const* d_in, const int* in_sizes, int n_in,
                              void* d_out, int out_size) {
    // metadata order:
    // 0: incoming_spikes (4096*1024 f32)
    // 1: A_sensory  2: B_sensory  3: C_sensory
    // 4: A_association 5: B_association 6: C_association
    // 7: A_executive 8: B_executive 9: C_executive
    const float* x  = (const float*)d_in[0];
    const float* Bs = (const float*)d_in[2];
    const float* Cs = (const float*)d_in[3];
    const float* Ba = (const float*)d_in[5];
    const float* Ca = (const float*)d_in[6];
    const float* Be = (const float*)d_in[8];
    const float* Ce = (const float*)d_in[9];
    float* out = (float*)d_out;

    int n_vec = out_size / 4;                      // float4 count
    int threads = 256;
    int per_block = threads * 4;                   // 1024 float4 per block
    int blocks = (n_vec + per_block - 1) / per_block;

    fused_masked_copy_kernel<<<blocks, threads>>>((const float4*)x, (float4*)out,
                                                  Bs, Cs, Ba, Ca, Be, Ce, n_vec);
}

// round 5
// speedup vs baseline: 1.1982x; 1.1982x over previous
#include <cuda_runtime.h>
#include <cstdint>

#define STATE_DIM 16
#define CHUNK_BYTES 16384
#define THREADS 128

__device__ __forceinline__ uint32_t smem_u32(const void* p) {
    uint32_t a;
    asm("{ .reg .u64 t; cvta.to.shared.u64 t, %1; cvt.u32.u64 %0, t; }" : "=r"(a) : "l"(p));
    return a;
}

// Per-CTA: one 16KB chunk. flag>0 -> TMA bulk copy GMEM->SMEM->GMEM (bit-exact,
// since x in {0,1} and f==1). flag==0 -> STG zeros, x never read.
__global__ void __launch_bounds__(THREADS, 8)
tma_gated_copy_kernel(const float* __restrict__ x, float* __restrict__ out,
                      const float* __restrict__ Bs, const float* __restrict__ Cs,
                      const float* __restrict__ Ba, const float* __restrict__ Ca,
                      const float* __restrict__ Be, const float* __restrict__ Ce,
                      long long total_bytes) {
    __shared__ alignas(128) char buf[CHUNK_BYTES];
    __shared__ alignas(8) uint64_t mbar;
    __shared__ float sflag;

    const int tid = threadIdx.x;
    const int lane = tid & 31;
    const long long off = (long long)blockIdx.x * CHUNK_BYTES;
    const uint32_t mbar_a = smem_u32(&mbar);
    const uint32_t buf_a = smem_u32(buf);

    // Warp 0: three 16-element dot products via shuffle reduction (L2-hot).
    if (tid < 32) {
        float p1 = 0.f, p2 = 0.f, p3 = 0.f;
        if (lane < STATE_DIM) {
            p1 = Bs[lane] * Cs[lane];
            p2 = Ba[lane] * Ca[lane];
            p3 = Be[lane] * Ce[lane];
        }
#pragma unroll
        for (int o = 8; o > 0; o >>= 1) {
            p1 += __shfl_down_sync(0xffffffffu, p1, o);
            p2 += __shfl_down_sync(0xffffffffu, p2, o);
            p3 += __shfl_down_sync(0xffffffffu, p3, o);
        }
        if (lane == 0)
            sflag = (p1 > 0.f && p2 > 0.f && p3 > 0.f) ? 1.0f : 0.0f;
    }
    if (tid == 0) {
        asm volatile("mbarrier.init.shared.b64 [%0], 1;" :: "r"(mbar_a) : "memory");
    }
    __syncthreads();

    const float f = sflag;
    const long long chunk = (off + CHUNK_BYTES <= total_bytes) ? CHUNK_BYTES
                                                               : (total_bytes - off);
    if (chunk <= 0) return;

    if (f > 0.f) {
        if (chunk == CHUNK_BYTES) {
            // Fast TMA path: full aligned chunk, single-thread issue.
            if (tid == 0) {
                asm volatile("mbarrier.arrive.expect_tx.shared.b64 _, [%0], %1;"
                             :: "r"(mbar_a), "r"((uint32_t)CHUNK_BYTES) : "memory");
                asm volatile("cp.async.bulk.shared::cta.global.mbarrier::complete_tx::bytes"
                             " [%0], [%1], %2, [%3];"
                             :: "r"(buf_a), "l"((const char*)x + off),
                                "r"((uint32_t)CHUNK_BYTES), "r"(mbar_a) : "memory");
                // Canonical bounded parity-wait loop (phase 0).
                asm volatile(
                    "{\n\t.reg .pred P1;\n\t"
                    "WAIT_LOOP_%=:\n\t"
                    "mbarrier.try_wait.parity.shared.b64 P1, [%0], 0, 0x989680;\n\t"
                    "@P1 bra.uni WAIT_DONE_%=;\n\t"
                    "bra.uni WAIT_LOOP_%=;\n\t"
                    "WAIT_DONE_%=:\n\t}"
                    :: "r"(mbar_a) : "memory");
                asm volatile("fence.proxy.async.shared::cta;" ::: "memory");
                asm volatile("cp.async.bulk.global.shared::cta.bulk_group [%0], [%1], %2;"
                             :: "l"((char*)out + off), "r"(buf_a),
                                "r"((uint32_t)CHUNK_BYTES) : "memory");
                asm volatile("cp.async.bulk.commit_group;" ::: "memory");
                asm volatile("cp.async.bulk.wait_group 0;" ::: "memory");
            }
        } else {
            // Tail path (not hit for benchmarked shape): plain elementwise copy.
            const float4* src = (const float4*)((const char*)x + off);
            float4* dst = (float4*)((char*)out + off);
            int nv = (int)(chunk / 16);
            for (int i = tid; i < nv; i += THREADS) dst[i] = src[i];
        }
    } else {
        // Gate closed: zero-fill, no reads of x.
        float4 z = make_float4(0.f, 0.f, 0.f, 0.f);
        float4* dst = (float4*)((char*)out + off);
        int nv = (int)(chunk / 16);   // 1024 float4 per full chunk
#pragma unroll
        for (int k = 0; k < CHUNK_BYTES / 16 / THREADS; ++k) {
            int i = tid + k * THREADS;
            if (i < nv) dst[i] = z;
        }
    }
}

extern "C" void kernel_launch(void* const* d_in, const int* in_sizes, int n_in,
                              void* d_out, int out_size) {
    // metadata order:
    // 0: incoming_spikes  1: A_sensory 2: B_sensory 3: C_sensory
    // 4: A_association 5: B_association 6: C_association
    // 7: A_executive 8: B_executive 9: C_executive
    const float* x  = (const float*)d_in[0];
    const float* Bs = (const float*)d_in[2];
    const float* Cs = (const float*)d_in[3];
    const float* Ba = (const float*)d_in[5];
    const float* Ca = (const float*)d_in[6];
    const float* Be = (const float*)d_in[8];
    const float* Ce = (const float*)d_in[9];
    float* out = (float*)d_out;

    long long total_bytes = (long long)out_size * 4;
    int blocks = (int)((total_bytes + CHUNK_BYTES - 1) / CHUNK_BYTES);  // 1024 for 16.7MB

    tma_gated_copy_kernel<<<blocks, THREADS>>>(x, out, Bs, Cs, Ba, Ca, Be, Ce,
                                               total_bytes);
}